// round 2
// baseline (speedup 1.0000x reference)
#include <cuda_runtime.h>
#include <math.h>

#define BATCH 8
#define CCH   64
#define HH    128
#define WWD   128
#define HWN   (HH*WWD)            // 16384
#define NEXP  3
#define NHEAD 16
#define NHID  16
#define OUTM  (BATCH*CCH*HWN)     // 8388608

// ---------------- scratch (static device globals; no runtime allocs) ----
__device__ float g_part[BATCH][32][4160];     // per-chunk partial Gram (4096) + channel sums (64)
__device__ float g_G[BATCH][4096];            // Gram matrices
__device__ float g_M1[BATCH][NEXP][4096];     // A @ Wv  (per batch, expert)
__device__ float g_R[BATCH][CCH][576];        // collapsed conv weights, layout [b][cin][tap*64+cout]
__device__ float g_logit[BATCH][NEXP];

// =========================================================================
// K1: partial Gram G_b = sum_p x[:,p] x[:,p]^T over a 512-pixel chunk,
//     plus per-channel partial sums (for the routing mean).
// grid (32, 8), 256 threads.
// =========================================================================
__global__ __launch_bounds__(256) void k_gram(const float* __restrict__ x) {
    int b = blockIdx.y, chunk = blockIdx.x;
    __shared__ __align__(16) float xs[64 * 68];   // [pixel][channel], stride 68
    int t  = threadIdx.x;
    int lc = t >> 2;              // load channel
    int lp = (t & 3) * 16;        // load pixel offset within 64-subtile
    int i0 = (t & 15) * 4;        // Gram tile row base
    int j0 = (t >> 4) * 4;        // Gram tile col base

    float acc[16];
#pragma unroll
    for (int k = 0; k < 16; k++) acc[k] = 0.f;
    float csum = 0.f;

    const float* xb = x + (size_t)b * CCH * HWN;
    int base = chunk * 512;

    for (int st = 0; st < 8; st++) {
        const float4* xp = reinterpret_cast<const float4*>(xb + lc * HWN + base + st * 64 + lp);
        float4 v0 = xp[0], v1 = xp[1], v2 = xp[2], v3 = xp[3];
        float tmp[16] = {v0.x, v0.y, v0.z, v0.w, v1.x, v1.y, v1.z, v1.w,
                         v2.x, v2.y, v2.z, v2.w, v3.x, v3.y, v3.z, v3.w};
#pragma unroll
        for (int i = 0; i < 16; i++) {
            csum += tmp[i];
            xs[(lp + i) * 68 + lc] = tmp[i];
        }
        __syncthreads();
#pragma unroll 8
        for (int p = 0; p < 64; p++) {
            float4 a  = *reinterpret_cast<const float4*>(&xs[p * 68 + i0]);
            float4 bb = *reinterpret_cast<const float4*>(&xs[p * 68 + j0]);
            acc[0]  = fmaf(a.x, bb.x, acc[0]);   acc[1]  = fmaf(a.x, bb.y, acc[1]);
            acc[2]  = fmaf(a.x, bb.z, acc[2]);   acc[3]  = fmaf(a.x, bb.w, acc[3]);
            acc[4]  = fmaf(a.y, bb.x, acc[4]);   acc[5]  = fmaf(a.y, bb.y, acc[5]);
            acc[6]  = fmaf(a.y, bb.z, acc[6]);   acc[7]  = fmaf(a.y, bb.w, acc[7]);
            acc[8]  = fmaf(a.z, bb.x, acc[8]);   acc[9]  = fmaf(a.z, bb.y, acc[9]);
            acc[10] = fmaf(a.z, bb.z, acc[10]);  acc[11] = fmaf(a.z, bb.w, acc[11]);
            acc[12] = fmaf(a.w, bb.x, acc[12]);  acc[13] = fmaf(a.w, bb.y, acc[13]);
            acc[14] = fmaf(a.w, bb.z, acc[14]);  acc[15] = fmaf(a.w, bb.w, acc[15]);
        }
        __syncthreads();
    }

    float* gp = g_part[b][chunk];
#pragma unroll
    for (int ii = 0; ii < 4; ii++)
#pragma unroll
        for (int jj = 0; jj < 4; jj++)
            gp[(i0 + ii) * 64 + (j0 + jj)] = acc[ii * 4 + jj];

    csum += __shfl_xor_sync(0xffffffffu, csum, 1);
    csum += __shfl_xor_sync(0xffffffffu, csum, 2);
    if ((t & 3) == 0) gp[4096 + lc] = csum;
}

// =========================================================================
// K2: reduce partials -> G_b, mean; routing MLP (gelu, relu); writes
//     hidden_new and logit outputs to the tail of d_out. grid 8, 256 thr.
// =========================================================================
__global__ __launch_bounds__(256) void k_route(const float* __restrict__ hidden,
                                               const float* __restrict__ r1w,
                                               const float* __restrict__ r1b,
                                               const float* __restrict__ r3w,
                                               const float* __restrict__ r3b,
                                               float* __restrict__ out, int out_size) {
    int b = blockIdx.x, t = threadIdx.x;
    __shared__ float mean[64];
    __shared__ float hg[16];

    for (int k = 0; k < 16; k++) {
        int idx = t + 256 * k;
        float s = 0.f;
        for (int ch = 0; ch < 32; ch++) s += g_part[b][ch][idx];
        g_G[b][idx] = s;
    }
    if (t < 64) {
        float s = 0.f;
        for (int ch = 0; ch < 32; ch++) s += g_part[b][ch][4096 + t];
        mean[t] = s * (1.0f / 16384.0f);
    }
    __syncthreads();
    if (t < 16) {
        float h = r1b[t];
        for (int c = 0; c < 64; c++) h = fmaf(mean[c], r1w[t * 80 + c], h);
        for (int j = 0; j < 16; j++) h = fmaf(hidden[b * 16 + j], r1w[t * 80 + 64 + j], h);
        float g = 0.5f * h * (1.0f + erff(h * 0.70710678118654752f));
        hg[t] = g;
        int oi = OUTM + b * 16 + t;
        if (oi < out_size) out[oi] = g;
    }
    __syncthreads();
    if (t < 3) {
        float v = r3b[t];
        for (int j = 0; j < 16; j++) v = fmaf(hg[j], r3w[t * 16 + j], v);
        v = fmaxf(v, 0.f);
        g_logit[b][t] = v;
        int oi = OUTM + 128 + b * 3 + t;
        if (oi < out_size) out[oi] = v;
    }
}

// =========================================================================
// K3: per (b,e): attention matrices via Gram trick, softmax, M1 = A @ Wv.
//     grid (3, 8), 256 threads.
// =========================================================================
__global__ __launch_bounds__(256) void k_attn(const float* __restrict__ qkvw,
                                              const float* __restrict__ temp) {
    int e = blockIdx.x, b = blockIdx.y, t = threadIdx.x;
    __shared__ float Gs[4096];
    __shared__ float tb[4096];      // holds tq, then reused for tk
    __shared__ float Sraw[256];
    __shared__ float nq[64], nk[64];
    __shared__ float A[64 * 4];

    const float* Wq = qkvw + (size_t)e * 192 * 64;
    const float* Wk = Wq + 64 * 64;
    const float* Wv = Wq + 128 * 64;

    for (int k = 0; k < 16; k++) Gs[t + 256 * k] = g_G[b][t + 256 * k];
    __syncthreads();

    int i  = t >> 2;
    int c0 = (t & 3) * 16;

    // tq = Wq @ G
    {
        float acc[16];
#pragma unroll
        for (int cc = 0; cc < 16; cc++) acc[cc] = 0.f;
        for (int m = 0; m < 64; m++) {
            float wq = __ldg(&Wq[i * 64 + m]);
            const float* gm = &Gs[m * 64 + c0];
#pragma unroll
            for (int cc = 0; cc < 16; cc++) acc[cc] = fmaf(wq, gm[cc], acc[cc]);
        }
#pragma unroll
        for (int cc = 0; cc < 16; cc++) tb[i * 64 + c0 + cc] = acc[cc];
    }
    __syncthreads();

    // nq and raw scores S (reads tq)
    if (t < 64) {
        float s = 0.f;
        for (int c = 0; c < 64; c++) s = fmaf(tb[t * 64 + c], __ldg(&Wq[t * 64 + c]), s);
        nq[t] = s;
    }
    {
        int h = t >> 4, a = (t >> 2) & 3, b2 = t & 3;
        int qi = h * 4 + a, kj = h * 4 + b2;
        float s = 0.f;
        for (int c = 0; c < 64; c++) s = fmaf(tb[qi * 64 + c], __ldg(&Wk[kj * 64 + c]), s);
        Sraw[t] = s;
    }
    // tk = Wk @ G (compute into regs before overwriting tb)
    float acck[16];
#pragma unroll
    for (int cc = 0; cc < 16; cc++) acck[cc] = 0.f;
    for (int m = 0; m < 64; m++) {
        float wk = __ldg(&Wk[i * 64 + m]);
        const float* gm = &Gs[m * 64 + c0];
#pragma unroll
        for (int cc = 0; cc < 16; cc++) acck[cc] = fmaf(wk, gm[cc], acck[cc]);
    }
    __syncthreads();
#pragma unroll
    for (int cc = 0; cc < 16; cc++) tb[i * 64 + c0 + cc] = acck[cc];
    __syncthreads();
    if (t < 64) {
        float s = 0.f;
        for (int c = 0; c < 64; c++) s = fmaf(tb[t * 64 + c], __ldg(&Wk[t * 64 + c]), s);
        nk[t] = s;
    }
    __syncthreads();

    // softmax row (h,a) with l2-norm scaling and temperature
    if (t < 64) {
        int h = t >> 2;
        float qn = fmaxf(sqrtf(nq[t]), 1e-12f);
        float tp = __ldg(&temp[e * 16 + h]);
        float v[4];
        float mx = -1e30f;
#pragma unroll
        for (int j = 0; j < 4; j++) {
            float kn = fmaxf(sqrtf(nk[h * 4 + j]), 1e-12f);
            v[j] = Sraw[h * 16 + (t & 3) * 4 + j] / (qn * kn) * tp;
            mx = fmaxf(mx, v[j]);
        }
        float s = 0.f;
#pragma unroll
        for (int j = 0; j < 4; j++) { v[j] = expf(v[j] - mx); s += v[j]; }
        float inv = 1.0f / s;
#pragma unroll
        for (int j = 0; j < 4; j++) A[t * 4 + j] = v[j] * inv;
    }
    __syncthreads();

    // M1[i][c] = sum_j A[i][j] * Wv[(i&~3)+j][c]
    {
        int hbase = (i >> 2) * 4;
        float a0 = A[i * 4], a1 = A[i * 4 + 1], a2 = A[i * 4 + 2], a3 = A[i * 4 + 3];
#pragma unroll
        for (int cc = 0; cc < 16; cc++) {
            int c = c0 + cc;
            float v = a0 * __ldg(&Wv[(hbase + 0) * 64 + c]);
            v = fmaf(a1, __ldg(&Wv[(hbase + 1) * 64 + c]), v);
            v = fmaf(a2, __ldg(&Wv[(hbase + 2) * 64 + c]), v);
            v = fmaf(a3, __ldg(&Wv[(hbase + 3) * 64 + c]), v);
            g_M1[b][e][i * 64 + c] = v;
        }
    }
}

// =========================================================================
// K4: R_t[o][c] = sum_e logit * sum_m P_e[o][m] * dw_e[m][t] * M1_e[m][c]
//     grid (9, 8), 256 threads. Output layout [b][c][t*64+o].
// =========================================================================
__global__ __launch_bounds__(256) void k_buildR(const float* __restrict__ projw,
                                                const float* __restrict__ dww) {
    int tap = blockIdx.x, b = blockIdx.y, t = threadIdx.x;
    __shared__ float M1s[4096];
    int o  = t & 63;
    int c0 = (t >> 6) * 16;
    float acc[16];
#pragma unroll
    for (int cc = 0; cc < 16; cc++) acc[cc] = 0.f;

    for (int e = 0; e < 3; e++) {
        __syncthreads();
        for (int k = 0; k < 16; k++) M1s[t + 256 * k] = g_M1[b][e][t + 256 * k];
        __syncthreads();
        float l = g_logit[b][e];
        const float* P  = projw + (size_t)e * 4096 + o * 64;
        const float* wd = dww + (size_t)e * 64 * 9;
        for (int m = 0; m < 64; m++) {
            float coef = l * __ldg(&P[m]) * __ldg(&wd[m * 9 + tap]);
            const float* mm = &M1s[m * 64 + c0];
#pragma unroll
            for (int cc = 0; cc < 16; cc++) acc[cc] = fmaf(coef, mm[cc], acc[cc]);
        }
    }
#pragma unroll
    for (int cc = 0; cc < 16; cc++) g_R[b][c0 + cc][tap * 64 + o] = acc[cc];
}

// =========================================================================
// K5: main fused kernel. out[b] = sum over 9 taps of R_t @ x(shifted).
//     Per-batch dense 3x3 conv, 64->64 channels, SAME padding.
//     Block: (2 rows x 128 cols) x 64 out-channels; thread: 4 oc x 16 px.
//     grid (64, 8), 256 threads, 2 blocks/SM.
// =========================================================================
__global__ __launch_bounds__(256, 2) void k_conv(const float* __restrict__ x,
                                                 float* __restrict__ out) {
    int b  = blockIdx.y;
    int y0 = blockIdx.x * 2;
    __shared__ __align__(16) float sx[4 * 132];   // rows y0-1..y0+2, cols -1..128 at idx 0..129
    __shared__ float sR[576];

    int t   = threadIdx.x;
    int oG  = t >> 4;          // 0..15 -> out-channel group of 4
    int pos = t & 15;
    int ty  = pos >> 3;        // 0..1
    int x0  = (pos & 7) * 16;  // 0..112
    int y   = y0 + ty;

    const float* xb = x + (size_t)b * 64 * HWN;
    const float* Rb = &g_R[b][0][0];   // [c][576]

    // cooperative-load index precompute (sx: 520 useful elems; sR: 576)
    // Three legs: t (0..255), t+256 (256..511), t+512 (512..519 for t<8).
    int li1 = t + 256;
    int li2 = t + 512;
    int lr0 = t / 130,   lc0v = t % 130;
    int lr1 = li1 / 130, lc1v = li1 % 130;
    int lr2 = li2 / 130, lc2v = li2 % 130;
    int gy0 = y0 - 1 + lr0, gx0 = lc0v - 1;
    int gy1 = y0 - 1 + lr1, gx1 = lc1v - 1;
    int gy2 = y0 - 1 + lr2, gx2 = lc2v - 1;
    bool v0 = (gy0 >= 0 && gy0 < 128 && gx0 >= 0 && gx0 < 128);
    bool v1 = (gy1 >= 0 && gy1 < 128 && gx1 >= 0 && gx1 < 128);
    bool x2ok = (li2 < 520);
    bool v2 = x2ok && (gy2 >= 0 && gy2 < 128 && gx2 >= 0 && gx2 < 128);
    int off0 = gy0 * 128 + gx0;
    int off1 = gy1 * 128 + gx1;
    int off2 = gy2 * 128 + gx2;
    bool rv2 = (t + 512) < 576;

    float acc[4][16];
#pragma unroll
    for (int a = 0; a < 4; a++)
#pragma unroll
        for (int p = 0; p < 16; p++) acc[a][p] = 0.f;

    // prefetch c = 0
    float px0 = v0 ? __ldg(&xb[off0]) : 0.f;
    float px1 = v1 ? __ldg(&xb[off1]) : 0.f;
    float px2 = v2 ? __ldg(&xb[off2]) : 0.f;
    float pr0 = __ldg(&Rb[t]);
    float pr1 = __ldg(&Rb[t + 256]);
    float pr2 = rv2 ? __ldg(&Rb[t + 512]) : 0.f;

    for (int c = 0; c < 64; c++) {
        __syncthreads();
        sx[lr0 * 132 + lc0v] = px0;
        sx[lr1 * 132 + lc1v] = px1;
        if (x2ok) sx[lr2 * 132 + lc2v] = px2;
        sR[t] = pr0;
        sR[t + 256] = pr1;
        if (rv2) sR[t + 512] = pr2;
        __syncthreads();

        if (c + 1 < 64) {
            const float* xc = xb + (size_t)(c + 1) * HWN;
            px0 = v0 ? __ldg(&xc[off0]) : 0.f;
            px1 = v1 ? __ldg(&xc[off1]) : 0.f;
            px2 = v2 ? __ldg(&xc[off2]) : 0.f;
            const float* rc = Rb + (size_t)(c + 1) * 576;
            pr0 = __ldg(&rc[t]);
            pr1 = __ldg(&rc[t + 256]);
            pr2 = rv2 ? __ldg(&rc[t + 512]) : 0.f;
        }

#pragma unroll
        for (int ky = 0; ky < 3; ky++) {
            const float* srow = &sx[(ty + ky) * 132 + x0];
            float xr[18];
#pragma unroll
            for (int q = 0; q < 4; q++) {
                float4 v = *reinterpret_cast<const float4*>(srow + q * 4);
                xr[q * 4] = v.x; xr[q * 4 + 1] = v.y; xr[q * 4 + 2] = v.z; xr[q * 4 + 3] = v.w;
            }
            xr[16] = srow[16];
            xr[17] = srow[17];
#pragma unroll
            for (int o4 = 0; o4 < 4; o4++) {
#pragma unroll
                for (int kx = 0; kx < 3; kx++) {
                    float r = sR[(ky * 3 + kx) * 64 + oG * 4 + o4];
#pragma unroll
                    for (int px = 0; px < 16; px++)
                        acc[o4][px] = fmaf(r, xr[px + kx], acc[o4][px]);
                }
            }
        }
    }

#pragma unroll
    for (int o4 = 0; o4 < 4; o4++) {
        float* op = out + (((size_t)b * 64 + oG * 4 + o4) * 128 + y) * 128 + x0;
#pragma unroll
        for (int q = 0; q < 4; q++) {
            float4 v = make_float4(acc[o4][q * 4], acc[o4][q * 4 + 1],
                                   acc[o4][q * 4 + 2], acc[o4][q * 4 + 3]);
            *reinterpret_cast<float4*>(op + q * 4) = v;
        }
    }
}

// =========================================================================
extern "C" void kernel_launch(void* const* d_in, const int* in_sizes, int n_in,
                              void* d_out, int out_size) {
    const float* x      = (const float*)d_in[0];
    const float* hidden = (const float*)d_in[1];
    const float* qkvw   = (const float*)d_in[2];
    const float* dww    = (const float*)d_in[3];
    const float* projw  = (const float*)d_in[4];
    const float* temp   = (const float*)d_in[5];
    const float* r1w    = (const float*)d_in[6];
    const float* r1b    = (const float*)d_in[7];
    const float* r3w    = (const float*)d_in[8];
    const float* r3b    = (const float*)d_in[9];
    float* out = (float*)d_out;

    k_gram<<<dim3(32, 8), 256>>>(x);
    k_route<<<8, 256>>>(hidden, r1w, r1b, r3w, r3b, out, out_size);
    k_attn<<<dim3(3, 8), 256>>>(qkvw, temp);
    k_buildR<<<dim3(9, 8), 256>>>(projw, dww);
    k_conv<<<dim3(64, 8), 256>>>(x, out);
}